// round 1
// baseline (speedup 1.0000x reference)
#include <cuda_runtime.h>
#include <math.h>

#define T_  1024
#define B_  2
#define E_  1024
#define H_  16
#define F_  8
#define D_  64
#define R_  2047
#define TB_ 2048
#define RB_ 4094

// ---------------- scratch (device globals: allocation-free) ----------------
__device__ float g_Win [3 * E_ * E_];    // 12.6 MB
__device__ float g_Wpos[E_ * E_];
__device__ float g_Wout[E_ * E_];
__device__ float g_bin [3 * E_];
__device__ float g_bpos[E_];
__device__ float g_bout[E_];
__device__ float g_rw  [E_];
__device__ float g_rr  [E_];
__device__ float g_qkv [TB_ * 3 * E_];   // 25 MB   [m = t*B+b][3E]
__device__ float g_r   [RB_ * E_];       // 16.8 MB [p*B+b][E]
__device__ float g_S   [33554432];       // 134 MB  [bh][T][T]
__device__ float g_att [TB_ * E_];       // 8.4 MB  [m][E]

// ---------------- hypernet GEMV: out[i] = dot(w[i, 0:8], factor) ----------------
__global__ __launch_bounds__(256) void hyper_kernel(const float* __restrict__ w,
                                                    const float* __restrict__ f,
                                                    float* __restrict__ out, int n)
{
    int i = blockIdx.x * blockDim.x + threadIdx.x;
    if (i >= n) return;
    const float4* wp = (const float4*)(w + (size_t)i * 8);
    float4 a = wp[0], b = wp[1];
    float4 f0 = *(const float4*)f;
    float4 f1 = *(const float4*)(f + 4);
    out[i] = a.x*f0.x + a.y*f0.y + a.z*f0.z + a.w*f0.w
           + b.x*f1.x + b.y*f1.y + b.z*f1.z + b.w*f1.w;
}

// ---------------- NT SGEMM with bias: C[m,n] = sum_k A[m,k]*Bm[n,k] + bias[n] ---
// BM=BN=64, BK=16, 256 threads, 4x4 microtile. N,K multiples of 64/16; M guarded.
__global__ __launch_bounds__(256) void gemm_nt(const float* __restrict__ A,
                                               const float* __restrict__ Bm,
                                               const float* __restrict__ bias,
                                               float* __restrict__ C,
                                               int M, int N, int K)
{
    __shared__ float As[16][64];
    __shared__ float Bs[16][64];
    int bm = blockIdx.y * 64, bn = blockIdx.x * 64;
    int tid = threadIdx.x;
    int lr = tid >> 2;            // 0..63
    int lc = (tid & 3) * 4;       // 0,4,8,12
    int ty = tid >> 4, tx = tid & 15;
    float acc[4][4] = {};

    for (int k0 = 0; k0 < K; k0 += 16) {
        int am = bm + lr;
        float4 av = make_float4(0.f, 0.f, 0.f, 0.f);
        if (am < M) av = *(const float4*)(A + (size_t)am * K + k0 + lc);
        float4 bv = *(const float4*)(Bm + (size_t)(bn + lr) * K + k0 + lc);
        As[lc + 0][lr] = av.x; As[lc + 1][lr] = av.y;
        As[lc + 2][lr] = av.z; As[lc + 3][lr] = av.w;
        Bs[lc + 0][lr] = bv.x; Bs[lc + 1][lr] = bv.y;
        Bs[lc + 2][lr] = bv.z; Bs[lc + 3][lr] = bv.w;
        __syncthreads();
#pragma unroll
        for (int kk = 0; kk < 16; kk++) {
            float4 a4 = *(const float4*)&As[kk][ty * 4];
            float4 b4 = *(const float4*)&Bs[kk][tx * 4];
            float ar[4] = {a4.x, a4.y, a4.z, a4.w};
            float br[4] = {b4.x, b4.y, b4.z, b4.w};
#pragma unroll
            for (int ii = 0; ii < 4; ii++)
#pragma unroll
                for (int jj = 0; jj < 4; jj++)
                    acc[ii][jj] += ar[ii] * br[jj];
        }
        __syncthreads();
    }

    float4 bb = *(const float4*)(bias + bn + tx * 4);
#pragma unroll
    for (int ii = 0; ii < 4; ii++) {
        int m = bm + ty * 4 + ii;
        if (m >= M) continue;
        float4 o;
        o.x = acc[ii][0] + bb.x; o.y = acc[ii][1] + bb.y;
        o.z = acc[ii][2] + bb.z; o.w = acc[ii][3] + bb.w;
        *(float4*)(C + (size_t)m * N + bn + tx * 4) = o;
    }
}

// ---------------- scores: S[bh,i,j] = (q+rw).k  +  (q+rr).r[j+T-1-i] -----------
// Block = (j-tile 64, i-tile 64, bh). The r window for a 64x64 tile spans exactly
// 127 consecutive relative positions [pmin, pmin+126], always in range.
__global__ __launch_bounds__(256) void scores_kernel(const float* __restrict__ qkv,
                                                     const float* __restrict__ rproj,
                                                     const float* __restrict__ rw,
                                                     const float* __restrict__ rr,
                                                     float* __restrict__ S)
{
    __shared__ float sQw[32][64];
    __shared__ float sQr[32][64];
    __shared__ float sK [32][64];
    __shared__ float sR [32][128];

    int bh = blockIdx.z;
    int b = bh / H_, h = bh % H_;
    int i0 = blockIdx.y * 64, j0 = blockIdx.x * 64;
    int pmin = j0 - i0 + (T_ - 64);           // min r index in this tile, >= 0
    int tid = threadIdx.x;
    int ty = tid >> 4, tx = tid & 15;
    int ib = ty * 4, jb = tx * 4;
    int pb = jb - ib + 63;                    // local r base (delta = 0)
    float acc[4][4] = {};

    for (int c = 0; c < 2; c++) {
        int dk0 = c * 32;
        for (int t = tid; t < 64 * 32; t += 256) {
            int il = t >> 5, d = t & 31;
            int col = h * D_ + dk0 + d;
            float qv = qkv[(size_t)((i0 + il) * B_ + b) * (3 * E_) + col];
            sQw[d][il] = qv + rw[col];
            sQr[d][il] = qv + rr[col];
            sK [d][il] = qkv[(size_t)((j0 + il) * B_ + b) * (3 * E_) + E_ + col];
        }
        for (int t = tid; t < 127 * 32; t += 256) {
            int pl = t >> 5, d = t & 31;
            sR[d][pl] = rproj[(size_t)((pmin + pl) * B_ + b) * E_ + h * D_ + dk0 + d];
        }
        __syncthreads();
#pragma unroll
        for (int kk = 0; kk < 32; kk++) {
            float4 qw4 = *(const float4*)&sQw[kk][ib];
            float4 qr4 = *(const float4*)&sQr[kk][ib];
            float4 kv4 = *(const float4*)&sK [kk][jb];
            float rv[7];
#pragma unroll
            for (int t2 = 0; t2 < 7; t2++) rv[t2] = sR[kk][pb - 3 + t2];
            float qwa[4] = {qw4.x, qw4.y, qw4.z, qw4.w};
            float qra[4] = {qr4.x, qr4.y, qr4.z, qr4.w};
            float ka [4] = {kv4.x, kv4.y, kv4.z, kv4.w};
#pragma unroll
            for (int ii = 0; ii < 4; ii++)
#pragma unroll
                for (int jj = 0; jj < 4; jj++)
                    acc[ii][jj] += qwa[ii] * ka[jj] + qra[ii] * rv[jj - ii + 3];
        }
        __syncthreads();
    }

#pragma unroll
    for (int ii = 0; ii < 4; ii++) {
        float4 o = {acc[ii][0], acc[ii][1], acc[ii][2], acc[ii][3]};
        *(float4*)&S[((size_t)bh * T_ + (i0 + ib + ii)) * T_ + j0 + jb] = o;
    }
}

// ---------------- softmax over last dim (row length 1024), scale = 1/8 ----------
__global__ __launch_bounds__(128) void softmax_kernel(float* __restrict__ S)
{
    __shared__ float redm[4], reds[4];
    size_t row = blockIdx.x;
    float* p = S + row * T_;
    int tid = threadIdx.x;
    int lane = tid & 31, warp = tid >> 5;

    float4 v0 = *(float4*)(p + tid * 8);
    float4 v1 = *(float4*)(p + tid * 8 + 4);
    float x[8] = {v0.x, v0.y, v0.z, v0.w, v1.x, v1.y, v1.z, v1.w};

    float m = x[0];
#pragma unroll
    for (int i = 1; i < 8; i++) m = fmaxf(m, x[i]);
#pragma unroll
    for (int o = 16; o > 0; o >>= 1) m = fmaxf(m, __shfl_xor_sync(0xffffffffu, m, o));
    if (lane == 0) redm[warp] = m;
    __syncthreads();
    m = fmaxf(fmaxf(redm[0], redm[1]), fmaxf(redm[2], redm[3]));

    const float sc = 0.125f;
    float s = 0.f;
#pragma unroll
    for (int i = 0; i < 8; i++) { x[i] = __expf((x[i] - m) * sc); s += x[i]; }
#pragma unroll
    for (int o = 16; o > 0; o >>= 1) s += __shfl_xor_sync(0xffffffffu, s, o);
    if (lane == 0) reds[warp] = s;
    __syncthreads();
    s = reds[0] + reds[1] + reds[2] + reds[3];
    float inv = 1.0f / s;

    v0.x = x[0]*inv; v0.y = x[1]*inv; v0.z = x[2]*inv; v0.w = x[3]*inv;
    v1.x = x[4]*inv; v1.y = x[5]*inv; v1.z = x[6]*inv; v1.w = x[7]*inv;
    *(float4*)(p + tid * 8)     = v0;
    *(float4*)(p + tid * 8 + 4) = v1;
}

// ---------------- PV: att[i,b,h,d] = sum_j P[bh,i,j] * v[j,b,h,d] ---------------
__global__ __launch_bounds__(256) void pv_kernel(const float* __restrict__ P,
                                                 const float* __restrict__ qkv,
                                                 float* __restrict__ att)
{
    __shared__ float sP[32][64];
    __shared__ float sV[32][64];
    int bh = blockIdx.y;
    int b = bh / H_, h = bh % H_;
    int i0 = blockIdx.x * 64;
    int tid = threadIdx.x;
    int ty = tid >> 4, tx = tid & 15;
    float acc[4][4] = {};

    for (int j0 = 0; j0 < T_; j0 += 32) {
        for (int t = tid; t < 64 * 8; t += 256) {
            int il = t >> 3, jc = (t & 7) * 4;
            float4 pv4 = *(const float4*)&P[((size_t)bh * T_ + i0 + il) * T_ + j0 + jc];
            sP[jc + 0][il] = pv4.x; sP[jc + 1][il] = pv4.y;
            sP[jc + 2][il] = pv4.z; sP[jc + 3][il] = pv4.w;
        }
        for (int t = tid; t < 32 * 64; t += 256) {
            int jl = t >> 6, d = t & 63;
            sV[jl][d] = qkv[(size_t)((j0 + jl) * B_ + b) * (3 * E_) + 2 * E_ + h * D_ + d];
        }
        __syncthreads();
#pragma unroll
        for (int kk = 0; kk < 32; kk++) {
            float4 p4 = *(const float4*)&sP[kk][ty * 4];
            float4 v4 = *(const float4*)&sV[kk][tx * 4];
            float pa[4] = {p4.x, p4.y, p4.z, p4.w};
            float va[4] = {v4.x, v4.y, v4.z, v4.w};
#pragma unroll
            for (int ii = 0; ii < 4; ii++)
#pragma unroll
                for (int jj = 0; jj < 4; jj++)
                    acc[ii][jj] += pa[ii] * va[jj];
        }
        __syncthreads();
    }

#pragma unroll
    for (int ii = 0; ii < 4; ii++) {
        float4 o = {acc[ii][0], acc[ii][1], acc[ii][2], acc[ii][3]};
        *(float4*)&att[(size_t)((i0 + ty * 4 + ii) * B_ + b) * E_ + h * D_ + tx * 4] = o;
    }
}

// ---------------- launch ----------------
extern "C" void kernel_launch(void* const* d_in, const int* in_sizes, int n_in,
                              void* d_out, int out_size)
{
    (void)in_sizes; (void)n_in; (void)out_size;
    const float* input  = (const float*)d_in[0];
    const float* pos    = (const float*)d_in[1];
    const float* factor = (const float*)d_in[2];
    const float* w_in   = (const float*)d_in[3];
    const float* w_pos  = (const float*)d_in[4];
    const float* w_out  = (const float*)d_in[5];
    const float* bw_in  = (const float*)d_in[6];
    const float* bw_pos = (const float*)d_in[7];
    const float* bw_out = (const float*)d_in[8];
    const float* rwb    = (const float*)d_in[9];
    const float* rrb    = (const float*)d_in[10];

    float *pWin, *pWpos, *pWout, *pbin, *pbpos, *pbout, *prw, *prr,
          *pqkv, *pr, *pS, *patt;
    cudaGetSymbolAddress((void**)&pWin,  g_Win);
    cudaGetSymbolAddress((void**)&pWpos, g_Wpos);
    cudaGetSymbolAddress((void**)&pWout, g_Wout);
    cudaGetSymbolAddress((void**)&pbin,  g_bin);
    cudaGetSymbolAddress((void**)&pbpos, g_bpos);
    cudaGetSymbolAddress((void**)&pbout, g_bout);
    cudaGetSymbolAddress((void**)&prw,   g_rw);
    cudaGetSymbolAddress((void**)&prr,   g_rr);
    cudaGetSymbolAddress((void**)&pqkv,  g_qkv);
    cudaGetSymbolAddress((void**)&pr,    g_r);
    cudaGetSymbolAddress((void**)&pS,    g_S);
    cudaGetSymbolAddress((void**)&patt,  g_att);

    // 1) hypernet contractions
    hyper_kernel<<<(3 * E_ * E_ + 255) / 256, 256>>>(w_in,  factor, pWin,  3 * E_ * E_);
    hyper_kernel<<<(E_ * E_ + 255) / 256,     256>>>(w_pos, factor, pWpos, E_ * E_);
    hyper_kernel<<<(E_ * E_ + 255) / 256,     256>>>(w_out, factor, pWout, E_ * E_);
    hyper_kernel<<<(3 * E_ + 255) / 256,      256>>>(bw_in,  factor, pbin,  3 * E_);
    hyper_kernel<<<(E_ + 255) / 256,          256>>>(bw_pos, factor, pbpos, E_);
    hyper_kernel<<<(E_ + 255) / 256,          256>>>(bw_out, factor, pbout, E_);
    hyper_kernel<<<(E_ + 255) / 256,          256>>>(rwb,    factor, prw,   E_);
    hyper_kernel<<<(E_ + 255) / 256,          256>>>(rrb,    factor, prr,   E_);

    // 2) projections
    gemm_nt<<<dim3(3 * E_ / 64, TB_ / 64), 256>>>(input, pWin,  pbin,  pqkv, TB_, 3 * E_, E_);
    gemm_nt<<<dim3(E_ / 64, (RB_ + 63) / 64), 256>>>(pos, pWpos, pbpos, pr,   RB_, E_,     E_);

    // 3) scores with fused relative shift
    scores_kernel<<<dim3(T_ / 64, T_ / 64, B_ * H_), 256>>>(pqkv, pr, prw, prr, pS);

    // 4) softmax (scale fused)
    softmax_kernel<<<B_ * H_ * T_, 128>>>(pS);

    // 5) attn @ V
    pv_kernel<<<dim3(T_ / 64, B_ * H_), 256>>>(pS, pqkv, patt);

    // 6) output projection -> d_out
    gemm_nt<<<dim3(E_ / 64, TB_ / 64), 256>>>(patt, pWout, pbout, (float*)d_out, TB_, E_, E_);
}

// round 3
// speedup vs baseline: 1.9998x; 1.9998x over previous
#include <cuda_runtime.h>
#include <math.h>

#define T_  1024
#define B_  2
#define E_  1024
#define H_  16
#define D_  64
#define R_  2047
#define TB_ 2048
#define RB_ 4094

// ---------------- scratch ----------------
__device__ float g_Win [3 * E_ * E_];
__device__ float g_Wpos[E_ * E_];
__device__ float g_Wout[E_ * E_];
__device__ float g_bin [3 * E_];
__device__ float g_bpos[E_];
__device__ float g_bout[E_];
__device__ float g_rw  [E_];
__device__ float g_rr  [E_];
__device__ float g_qkv [TB_ * 3 * E_];
__device__ float g_r   [RB_ * E_];
__device__ float g_S   [33554432];
__device__ float g_att [TB_ * E_];

// ---------------- tf32 helpers ----------------
__device__ __forceinline__ unsigned f2tf(float f) {
    unsigned r; asm("cvt.rna.tf32.f32 %0, %1;" : "=r"(r) : "f"(f)); return r;
}
// v = hi + lo, hi/lo both valid tf32 encodings; v-hi is exact in fp32
__device__ __forceinline__ void split2(float v, float& hi, float& lo) {
    hi = __uint_as_float(f2tf(v));
    lo = __uint_as_float(f2tf(v - hi));
}
__device__ __forceinline__ void mma8(float* c, const float* a, const float* b) {
    asm volatile("mma.sync.aligned.m16n8k8.row.col.f32.tf32.tf32.f32 "
                 "{%0,%1,%2,%3},{%4,%5,%6,%7},{%8,%9},{%0,%1,%2,%3};"
                 : "+f"(c[0]), "+f"(c[1]), "+f"(c[2]), "+f"(c[3])
                 : "r"(__float_as_uint(a[0])), "r"(__float_as_uint(a[1])),
                   "r"(__float_as_uint(a[2])), "r"(__float_as_uint(a[3])),
                   "r"(__float_as_uint(b[0])), "r"(__float_as_uint(b[1])));
}
// 3xtf32: c += ah*bh + ah*bl + al*bh
__device__ __forceinline__ void mma3(float* c, const float* ah, const float* al,
                                     const float* bh, const float* bl) {
    mma8(c, ah, bh);
    mma8(c, ah, bl);
    mma8(c, al, bh);
}

// ---------------- hypernet GEMV ----------------
__global__ __launch_bounds__(256) void hyper_kernel(const float* __restrict__ w,
                                                    const float* __restrict__ f,
                                                    float* __restrict__ out, int n)
{
    int i = blockIdx.x * blockDim.x + threadIdx.x;
    if (i >= n) return;
    const float4* wp = (const float4*)(w + (size_t)i * 8);
    float4 a = wp[0], b = wp[1];
    float4 f0 = *(const float4*)f;
    float4 f1 = *(const float4*)(f + 4);
    out[i] = a.x*f0.x + a.y*f0.y + a.z*f0.z + a.w*f0.w
           + b.x*f1.x + b.y*f1.y + b.z*f1.z + b.w*f1.w;
}

// ---------------- 3xtf32 NT GEMM: C[m,n] = sum_k A[m,k]*Bm[n,k] + bias[n] ------
// BM=128, BN=128, BK=32, 256 threads, warp tile 64x32 (2x4 warp grid)
#define GA_H 0
#define GA_L 4608
#define GB_H 9216
#define GB_L 13824
#define GEMM_SMEM (18432 * 4)

__global__ __launch_bounds__(256) void gemm3(const float* __restrict__ A,
                                             const float* __restrict__ Bm,
                                             const float* __restrict__ bias,
                                             float* __restrict__ C,
                                             int M, int N, int K)
{
    extern __shared__ float sm[];
    int bm = blockIdx.y * 128, bn = blockIdx.x * 128;
    int tid = threadIdx.x;
    int w = tid >> 5, lane = tid & 31;
    int g = lane >> 2, tg = lane & 3;
    int wm = w & 1, wn = w >> 1;
    float acc[4][4][4] = {};

    for (int k0 = 0; k0 < K; k0 += 32) {
#pragma unroll
        for (int it = 0; it < 4; it++) {
            int t = tid + 256 * it;
            int row = t >> 3, kq = (t & 7) << 2;
            int m = bm + row;
            float4 av = (m < M) ? *(const float4*)(A + (size_t)m * K + k0 + kq)
                                : make_float4(0.f, 0.f, 0.f, 0.f);
            float4 ah, al;
            split2(av.x, ah.x, al.x); split2(av.y, ah.y, al.y);
            split2(av.z, ah.z, al.z); split2(av.w, ah.w, al.w);
            *(float4*)&sm[GA_H + row * 36 + kq] = ah;
            *(float4*)&sm[GA_L + row * 36 + kq] = al;
            float4 bv = *(const float4*)(Bm + (size_t)(bn + row) * K + k0 + kq);
            float4 bh, bl;
            split2(bv.x, bh.x, bl.x); split2(bv.y, bh.y, bl.y);
            split2(bv.z, bh.z, bl.z); split2(bv.w, bh.w, bl.w);
            *(float4*)&sm[GB_H + row * 36 + kq] = bh;
            *(float4*)&sm[GB_L + row * 36 + kq] = bl;
        }
        __syncthreads();
#pragma unroll
        for (int ks = 0; ks < 4; ks++) {
            float ah[4][4], al[4][4], bh[4][2], bl[4][2];
#pragma unroll
            for (int mi = 0; mi < 4; mi++) {
                int r0 = (wm * 64 + mi * 16 + g) * 36 + ks * 8 + tg;
                ah[mi][0] = sm[GA_H + r0];
                ah[mi][1] = sm[GA_H + r0 + 8 * 36];
                ah[mi][2] = sm[GA_H + r0 + 4];
                ah[mi][3] = sm[GA_H + r0 + 8 * 36 + 4];
                al[mi][0] = sm[GA_L + r0];
                al[mi][1] = sm[GA_L + r0 + 8 * 36];
                al[mi][2] = sm[GA_L + r0 + 4];
                al[mi][3] = sm[GA_L + r0 + 8 * 36 + 4];
            }
#pragma unroll
            for (int ni = 0; ni < 4; ni++) {
                int r0 = (wn * 32 + ni * 8 + g) * 36 + ks * 8 + tg;
                bh[ni][0] = sm[GB_H + r0];
                bh[ni][1] = sm[GB_H + r0 + 4];
                bl[ni][0] = sm[GB_L + r0];
                bl[ni][1] = sm[GB_L + r0 + 4];
            }
#pragma unroll
            for (int mi = 0; mi < 4; mi++)
#pragma unroll
                for (int ni = 0; ni < 4; ni++)
                    mma3(acc[mi][ni], ah[mi], al[mi], bh[ni], bl[ni]);
        }
        __syncthreads();
    }

#pragma unroll
    for (int mi = 0; mi < 4; mi++)
#pragma unroll
        for (int ni = 0; ni < 4; ni++) {
            int m0 = bm + wm * 64 + mi * 16 + g;
            int n0 = bn + wn * 32 + ni * 8 + tg * 2;
            float bb0 = bias[n0], bb1 = bias[n0 + 1];
            if (m0 < M) {
                float2 o = {acc[mi][ni][0] + bb0, acc[mi][ni][1] + bb1};
                *(float2*)(C + (size_t)m0 * N + n0) = o;
            }
            if (m0 + 8 < M) {
                float2 o = {acc[mi][ni][2] + bb0, acc[mi][ni][3] + bb1};
                *(float2*)(C + (size_t)(m0 + 8) * N + n0) = o;
            }
        }
}

// ---------------- scores (3xtf32 mma, fused rel-shift) -------------------------
// Block: 64(i) x 64(j) per bh. 128 threads = 4 warps (2 wi x 2 wj).
// AC = (q+rw).k^T (64x64); G[i][p] = (q+rr).rwin[p]^T (64x128 window GEMM);
// S[i][j] = AC[i][j] + G[i][j-i+63]. K chunks of 16.
#define SQWH 0
#define SQWL 1280
#define SQRH 2560
#define SQRL 3840
#define SKH  5120
#define SKL  6400
#define SRH  7680
#define SRL  10240
#define SGS  12800
#define SCORES_SMEM ((12800 + 64 * 132) * 4)

__global__ __launch_bounds__(128) void scores3(const float* __restrict__ qkv,
                                               const float* __restrict__ rproj,
                                               const float* __restrict__ rw,
                                               const float* __restrict__ rr,
                                               float* __restrict__ S)
{
    extern __shared__ float sm[];
    int bh = blockIdx.z;
    int b = bh / H_, h = bh % H_;
    int i0 = blockIdx.y * 64, j0 = blockIdx.x * 64;
    int pmin = j0 - i0 + (T_ - 64);
    int tid = threadIdx.x;
    int w = tid >> 5, lane = tid & 31;
    int g = lane >> 2, tg = lane & 3;
    int wi = w >> 1, wj = w & 1;

    float accA[2][4][4] = {};
    float accG[2][8][4] = {};

    for (int c = 0; c < 4; c++) {
        int col0 = h * D_ + c * 16;
        // q+rw (hi/lo), q+rr (hi/lo): 64 rows x 16
#pragma unroll
        for (int it = 0; it < 2; it++) {
            int t = tid + 128 * it;
            int il = t >> 2, kq = (t & 3) << 2;
            float4 qv = *(const float4*)(qkv + (size_t)((i0 + il) * B_ + b) * (3 * E_) + col0 + kq);
            float4 rwv = *(const float4*)(rw + col0 + kq);
            float4 rrv = *(const float4*)(rr + col0 + kq);
            float4 hw, lw, hr, lr;
            split2(qv.x + rwv.x, hw.x, lw.x); split2(qv.y + rwv.y, hw.y, lw.y);
            split2(qv.z + rwv.z, hw.z, lw.z); split2(qv.w + rwv.w, hw.w, lw.w);
            split2(qv.x + rrv.x, hr.x, lr.x); split2(qv.y + rrv.y, hr.y, lr.y);
            split2(qv.z + rrv.z, hr.z, lr.z); split2(qv.w + rrv.w, hr.w, lr.w);
            *(float4*)&sm[SQWH + il * 20 + kq] = hw;
            *(float4*)&sm[SQWL + il * 20 + kq] = lw;
            *(float4*)&sm[SQRH + il * 20 + kq] = hr;
            *(float4*)&sm[SQRL + il * 20 + kq] = lr;
        }
        // k: 64 rows x 16
#pragma unroll
        for (int it = 0; it < 2; it++) {
            int t = tid + 128 * it;
            int il = t >> 2, kq = (t & 3) << 2;
            float4 kv = *(const float4*)(qkv + (size_t)((j0 + il) * B_ + b) * (3 * E_) + E_ + col0 + kq);
            float4 hk, lk;
            split2(kv.x, hk.x, lk.x); split2(kv.y, hk.y, lk.y);
            split2(kv.z, hk.z, lk.z); split2(kv.w, hk.w, lk.w);
            *(float4*)&sm[SKH + il * 20 + kq] = hk;
            *(float4*)&sm[SKL + il * 20 + kq] = lk;
        }
        // r window: 127 rows x 16 (row 127 zeroed)
#pragma unroll
        for (int it = 0; it < 4; it++) {
            int t = tid + 128 * it;
            int pl = t >> 2, kq = (t & 3) << 2;
            float4 rv = (pl < 127)
                ? *(const float4*)(rproj + (size_t)((pmin + pl) * B_ + b) * E_ + col0 + kq)
                : make_float4(0.f, 0.f, 0.f, 0.f);
            float4 hh, ll;
            split2(rv.x, hh.x, ll.x); split2(rv.y, hh.y, ll.y);
            split2(rv.z, hh.z, ll.z); split2(rv.w, hh.w, ll.w);
            *(float4*)&sm[SRH + pl * 20 + kq] = hh;
            *(float4*)&sm[SRL + pl * 20 + kq] = ll;
        }
        __syncthreads();
#pragma unroll
        for (int ks = 0; ks < 2; ks++) {
            float aWh[2][4], aWl[2][4], aRh[2][4], aRl[2][4];
#pragma unroll
            for (int mi = 0; mi < 2; mi++) {
                int r0 = (wi * 32 + mi * 16 + g) * 20 + ks * 8 + tg;
                aWh[mi][0] = sm[SQWH + r0];
                aWh[mi][1] = sm[SQWH + r0 + 8 * 20];
                aWh[mi][2] = sm[SQWH + r0 + 4];
                aWh[mi][3] = sm[SQWH + r0 + 8 * 20 + 4];
                aWl[mi][0] = sm[SQWL + r0];
                aWl[mi][1] = sm[SQWL + r0 + 8 * 20];
                aWl[mi][2] = sm[SQWL + r0 + 4];
                aWl[mi][3] = sm[SQWL + r0 + 8 * 20 + 4];
                aRh[mi][0] = sm[SQRH + r0];
                aRh[mi][1] = sm[SQRH + r0 + 8 * 20];
                aRh[mi][2] = sm[SQRH + r0 + 4];
                aRh[mi][3] = sm[SQRH + r0 + 8 * 20 + 4];
                aRl[mi][0] = sm[SQRL + r0];
                aRl[mi][1] = sm[SQRL + r0 + 8 * 20];
                aRl[mi][2] = sm[SQRL + r0 + 4];
                aRl[mi][3] = sm[SQRL + r0 + 8 * 20 + 4];
            }
#pragma unroll
            for (int nj = 0; nj < 4; nj++) {
                float bh[2], bl[2];
                int r0 = (wj * 32 + nj * 8 + g) * 20 + ks * 8 + tg;
                bh[0] = sm[SKH + r0]; bh[1] = sm[SKH + r0 + 4];
                bl[0] = sm[SKL + r0]; bl[1] = sm[SKL + r0 + 4];
                mma3(accA[0][nj], aWh[0], aWl[0], bh, bl);
                mma3(accA[1][nj], aWh[1], aWl[1], bh, bl);
            }
#pragma unroll
            for (int ng = 0; ng < 8; ng++) {
                float bh[2], bl[2];
                int r0 = (wj * 64 + ng * 8 + g) * 20 + ks * 8 + tg;
                bh[0] = sm[SRH + r0]; bh[1] = sm[SRH + r0 + 4];
                bl[0] = sm[SRL + r0]; bl[1] = sm[SRL + r0 + 4];
                mma3(accG[0][ng], aRh[0], aRl[0], bh, bl);
                mma3(accG[1][ng], aRh[1], aRl[1], bh, bl);
            }
        }
        __syncthreads();
    }

    // stage G in shared
#pragma unroll
    for (int mi = 0; mi < 2; mi++)
#pragma unroll
        for (int ng = 0; ng < 8; ng++) {
            int r0 = wi * 32 + mi * 16 + g;
            int cc = wj * 64 + ng * 8 + tg * 2;
            sm[SGS + r0 * 132 + cc]           = accG[mi][ng][0];
            sm[SGS + r0 * 132 + cc + 1]       = accG[mi][ng][1];
            sm[SGS + (r0 + 8) * 132 + cc]     = accG[mi][ng][2];
            sm[SGS + (r0 + 8) * 132 + cc + 1] = accG[mi][ng][3];
        }
    __syncthreads();

    // S = AC + shifted G
#pragma unroll
    for (int mi = 0; mi < 2; mi++)
#pragma unroll
        for (int nj = 0; nj < 4; nj++) {
            int il = wi * 32 + mi * 16 + g;
            int jl = wj * 32 + nj * 8 + tg * 2;
            {
                float g0 = sm[SGS + il * 132 + (jl - il + 63)];
                float g1 = sm[SGS + il * 132 + (jl + 1 - il + 63)];
                float2 o = {accA[mi][nj][0] + g0, accA[mi][nj][1] + g1};
                *(float2*)&S[((size_t)bh * T_ + (i0 + il)) * T_ + j0 + jl] = o;
            }
            {
                int il2 = il + 8;
                float g0 = sm[SGS + il2 * 132 + (jl - il2 + 63)];
                float g1 = sm[SGS + il2 * 132 + (jl + 1 - il2 + 63)];
                float2 o = {accA[mi][nj][2] + g0, accA[mi][nj][3] + g1};
                *(float2*)&S[((size_t)bh * T_ + (i0 + il2)) * T_ + j0 + jl] = o;
            }
        }
}

// ---------------- softmax (scale fused) ----------------
__global__ __launch_bounds__(128) void softmax_kernel(float* __restrict__ S)
{
    __shared__ float redm[4], reds[4];
    size_t row = blockIdx.x;
    float* p = S + row * T_;
    int tid = threadIdx.x;
    int lane = tid & 31, warp = tid >> 5;

    float4 v0 = *(float4*)(p + tid * 8);
    float4 v1 = *(float4*)(p + tid * 8 + 4);
    float x[8] = {v0.x, v0.y, v0.z, v0.w, v1.x, v1.y, v1.z, v1.w};

    float m = x[0];
#pragma unroll
    for (int i = 1; i < 8; i++) m = fmaxf(m, x[i]);
#pragma unroll
    for (int o = 16; o > 0; o >>= 1) m = fmaxf(m, __shfl_xor_sync(0xffffffffu, m, o));
    if (lane == 0) redm[warp] = m;
    __syncthreads();
    m = fmaxf(fmaxf(redm[0], redm[1]), fmaxf(redm[2], redm[3]));

    const float sc = 0.125f;
    float s = 0.f;
#pragma unroll
    for (int i = 0; i < 8; i++) { x[i] = __expf((x[i] - m) * sc); s += x[i]; }
#pragma unroll
    for (int o = 16; o > 0; o >>= 1) s += __shfl_xor_sync(0xffffffffu, s, o);
    if (lane == 0) reds[warp] = s;
    __syncthreads();
    s = reds[0] + reds[1] + reds[2] + reds[3];
    float inv = 1.0f / s;

    v0.x = x[0]*inv; v0.y = x[1]*inv; v0.z = x[2]*inv; v0.w = x[3]*inv;
    v1.x = x[4]*inv; v1.y = x[5]*inv; v1.z = x[6]*inv; v1.w = x[7]*inv;
    *(float4*)(p + tid * 8)     = v0;
    *(float4*)(p + tid * 8 + 4) = v1;
}

// ---------------- PV (3xtf32): att[i,b,h,d] = sum_j P[bh,i,j] v[j,b,h,d] ------
// BM=128, BN=64(=D), BK=32, 256 threads, warp tile 32x32 (4m x 2n)
#define PH 0
#define PL 4608
#define VH 9216
#define VL 11392
#define PV_SMEM (13568 * 4)

__global__ __launch_bounds__(256) void pv3(const float* __restrict__ P,
                                           const float* __restrict__ qkv,
                                           float* __restrict__ att)
{
    extern __shared__ float sm[];
    int bh = blockIdx.y;
    int b = bh / H_, h = bh % H_;
    int i0 = blockIdx.x * 128;
    int tid = threadIdx.x;
    int w = tid >> 5, lane = tid & 31;
    int g = lane >> 2, tg = lane & 3;
    int wm = w & 3, wn = w >> 2;
    float acc[2][4][4] = {};

    for (int j0 = 0; j0 < T_; j0 += 32) {
#pragma unroll
        for (int it = 0; it < 4; it++) {
            int t = tid + 256 * it;
            int row = t >> 3, kq = (t & 7) << 2;
            float4 pv = *(const float4*)(P + ((size_t)bh * T_ + i0 + row) * T_ + j0 + kq);
            float4 hh, ll;
            split2(pv.x, hh.x, ll.x); split2(pv.y, hh.y, ll.y);
            split2(pv.z, hh.z, ll.z); split2(pv.w, hh.w, ll.w);
            *(float4*)&sm[PH + row * 36 + kq] = hh;
            *(float4*)&sm[PL + row * 36 + kq] = ll;
        }
#pragma unroll
        for (int it = 0; it < 2; it++) {
            int t = tid + 256 * it;
            int row = t >> 4, dq = (t & 15) << 2;
            float4 vv = *(const float4*)(qkv + (size_t)((j0 + row) * B_ + b) * (3 * E_) + 2 * E_ + h * D_ + dq);
            float4 hh, ll;
            split2(vv.x, hh.x, ll.x); split2(vv.y, hh.y, ll.y);
            split2(vv.z, hh.z, ll.z); split2(vv.w, hh.w, ll.w);
            *(float4*)&sm[VH + row * 68 + dq] = hh;
            *(float4*)&sm[VL + row * 68 + dq] = ll;
        }
        __syncthreads();
#pragma unroll
        for (int ks = 0; ks < 4; ks++) {
            float ah[2][4], al[2][4], bh[4][2], bl[4][2];
#pragma unroll
            for (int mi = 0; mi < 2; mi++) {
                int r0 = (wm * 32 + mi * 16 + g) * 36 + ks * 8 + tg;
                ah[mi][0] = sm[PH + r0];
                ah[mi][1] = sm[PH + r0 + 8 * 36];
                ah[mi][2] = sm[PH + r0 + 4];
                ah[mi][3] = sm[PH + r0 + 8 * 36 + 4];
                al[mi][0] = sm[PL + r0];
                al[mi][1] = sm[PL + r0 + 8 * 36];
                al[mi][2] = sm[PL + r0 + 4];
                al[mi][3] = sm[PL + r0 + 8 * 36 + 4];
            }
#pragma unroll
            for (int ni = 0; ni < 4; ni++) {
                int nb = wn * 32 + ni * 8 + g;
                bh[ni][0] = sm[VH + (ks * 8 + tg) * 68 + nb];
                bh[ni][1] = sm[VH + (ks * 8 + tg + 4) * 68 + nb];
                bl[ni][0] = sm[VL + (ks * 8 + tg) * 68 + nb];
                bl[ni][1] = sm[VL + (ks * 8 + tg + 4) * 68 + nb];
            }
#pragma unroll
            for (int mi = 0; mi < 2; mi++)
#pragma unroll
                for (int ni = 0; ni < 4; ni++)
                    mma3(acc[mi][ni], ah[mi], al[mi], bh[ni], bl[ni]);
        }
        __syncthreads();
    }

#pragma unroll
    for (int mi = 0; mi < 2; mi++)
#pragma unroll
        for (int ni = 0; ni < 4; ni++) {
            int m0 = i0 + wm * 32 + mi * 16 + g;
            int n0 = h * D_ + wn * 32 + ni * 8 + tg * 2;
            float2 o0 = {acc[mi][ni][0], acc[mi][ni][1]};
            float2 o1 = {acc[mi][ni][2], acc[mi][ni][3]};
            *(float2*)(att + (size_t)(m0 * B_ + b) * E_ + n0) = o0;
            *(float2*)(att + (size_t)((m0 + 8) * B_ + b) * E_ + n0) = o1;
        }
}

// ---------------- launch ----------------
extern "C" void kernel_launch(void* const* d_in, const int* in_sizes, int n_in,
                              void* d_out, int out_size)
{
    (void)in_sizes; (void)n_in; (void)out_size;
    const float* input  = (const float*)d_in[0];
    const float* pos    = (const float*)d_in[1];
    const float* factor = (const float*)d_in[2];
    const float* w_in   = (const float*)d_in[3];
    const float* w_pos  = (const float*)d_in[4];
    const float* w_out  = (const float*)d_in[5];
    const float* bw_in  = (const float*)d_in[6];
    const float* bw_pos = (const float*)d_in[7];
    const float* bw_out = (const float*)d_in[8];
    const float* rwb    = (const float*)d_in[9];
    const float* rrb    = (const float*)d_in[10];

    float *pWin, *pWpos, *pWout, *pbin, *pbpos, *pbout, *prw, *prr,
          *pqkv, *pr, *pS, *patt;
    cudaGetSymbolAddress((void**)&pWin,  g_Win);
    cudaGetSymbolAddress((void**)&pWpos, g_Wpos);
    cudaGetSymbolAddress((void**)&pWout, g_Wout);
    cudaGetSymbolAddress((void**)&pbin,  g_bin);
    cudaGetSymbolAddress((void**)&pbpos, g_bpos);
    cudaGetSymbolAddress((void**)&pbout, g_bout);
    cudaGetSymbolAddress((void**)&prw,   g_rw);
    cudaGetSymbolAddress((void**)&prr,   g_rr);
    cudaGetSymbolAddress((void**)&pqkv,  g_qkv);
    cudaGetSymbolAddress((void**)&pr,    g_r);
    cudaGetSymbolAddress((void**)&pS,    g_S);
    cudaGetSymbolAddress((void**)&patt,  g_att);

    cudaFuncSetAttribute(gemm3,   cudaFuncAttributeMaxDynamicSharedMemorySize, GEMM_SMEM);
    cudaFuncSetAttribute(scores3, cudaFuncAttributeMaxDynamicSharedMemorySize, SCORES_SMEM);
    cudaFuncSetAttribute(pv3,     cudaFuncAttributeMaxDynamicSharedMemorySize, PV_SMEM);

    // 1) hypernet
    hyper_kernel<<<(3 * E_ * E_ + 255) / 256, 256>>>(w_in,  factor, pWin,  3 * E_ * E_);
    hyper_kernel<<<(E_ * E_ + 255) / 256,     256>>>(w_pos, factor, pWpos, E_ * E_);
    hyper_kernel<<<(E_ * E_ + 255) / 256,     256>>>(w_out, factor, pWout, E_ * E_);
    hyper_kernel<<<(3 * E_ + 255) / 256,      256>>>(bw_in,  factor, pbin,  3 * E_);
    hyper_kernel<<<(E_ + 255) / 256,          256>>>(bw_pos, factor, pbpos, E_);
    hyper_kernel<<<(E_ + 255) / 256,          256>>>(bw_out, factor, pbout, E_);
    hyper_kernel<<<(E_ + 255) / 256,          256>>>(rwb,    factor, prw,   E_);
    hyper_kernel<<<(E_ + 255) / 256,          256>>>(rrb,    factor, prr,   E_);

    // 2) projections (3xtf32)
    gemm3<<<dim3(3 * E_ / 128, TB_ / 128), 256, GEMM_SMEM>>>(input, pWin, pbin, pqkv, TB_, 3 * E_, E_);
    gemm3<<<dim3(E_ / 128, (RB_ + 127) / 128), 256, GEMM_SMEM>>>(pos, pWpos, pbpos, pr, RB_, E_, E_);

    // 3) scores with fused relative shift (3xtf32)
    scores3<<<dim3(T_ / 64, T_ / 64, B_ * H_), 128, SCORES_SMEM>>>(pqkv, pr, prw, prr, pS);

    // 4) softmax
    softmax_kernel<<<B_ * H_ * T_, 128>>>(pS);

    // 5) attn @ V (3xtf32)
    pv3<<<dim3(T_ / 128, B_ * H_), 256, PV_SMEM>>>(pS, pqkv, patt);

    // 6) output projection -> d_out
    gemm3<<<dim3(E_ / 128, TB_ / 128), 256, GEMM_SMEM>>>(patt, pWout, pbout, (float*)d_out, TB_, E_, E_);
}

// round 5
// speedup vs baseline: 2.0654x; 1.0328x over previous
#include <cuda_runtime.h>
#include <math.h>

#define T_  1024
#define B_  2
#define E_  1024
#define H_  16
#define D_  64
#define TB_ 2048
#define RB_ 4094

// ---------------- scratch ----------------
__device__ float g_Win [3 * E_ * E_];
__device__ float g_Wpos[E_ * E_];
__device__ float g_Wout[E_ * E_];
__device__ float g_bin [3 * E_];
__device__ float g_bpos[E_];
__device__ float g_bout[E_];
__device__ float g_rw  [E_];
__device__ float g_rr  [E_];
__device__ float g_qkv [TB_ * 3 * E_];
__device__ float g_r   [RB_ * E_];
__device__ float g_att [TB_ * E_];

// ---------------- tf32 helpers ----------------
__device__ __forceinline__ unsigned f2tf(float f) {
    unsigned r; asm("cvt.rna.tf32.f32 %0, %1;" : "=r"(r) : "f"(f)); return r;
}
__device__ __forceinline__ void split2(float v, float& hi, float& lo) {
    hi = __uint_as_float(f2tf(v));
    lo = __uint_as_float(f2tf(v - hi));
}
__device__ __forceinline__ void mma8(float* c, const float* a, const float* b) {
    asm volatile("mma.sync.aligned.m16n8k8.row.col.f32.tf32.tf32.f32 "
                 "{%0,%1,%2,%3},{%4,%5,%6,%7},{%8,%9},{%0,%1,%2,%3};"
                 : "+f"(c[0]), "+f"(c[1]), "+f"(c[2]), "+f"(c[3])
                 : "r"(__float_as_uint(a[0])), "r"(__float_as_uint(a[1])),
                   "r"(__float_as_uint(a[2])), "r"(__float_as_uint(a[3])),
                   "r"(__float_as_uint(b[0])), "r"(__float_as_uint(b[1])));
}
__device__ __forceinline__ void mma3(float* c, const float* ah, const float* al,
                                     const float* bh, const float* bl) {
    mma8(c, ah, bh);
    mma8(c, ah, bl);
    mma8(c, al, bh);
}

// ---------------- fused hypernet: all 8 contractions in one launch -------------
#define HN0 3145728
#define HN1 (HN0 + 1048576)
#define HN2 (HN1 + 1048576)
#define HN3 (HN2 + 3072)
#define HN4 (HN3 + 1024)
#define HN5 (HN4 + 1024)
#define HN6 (HN5 + 1024)
#define HN7 (HN6 + 1024)

__global__ __launch_bounds__(256) void hyper_all(
    const float* __restrict__ w_in,  const float* __restrict__ w_pos,
    const float* __restrict__ w_out, const float* __restrict__ b_in,
    const float* __restrict__ b_pos, const float* __restrict__ b_out,
    const float* __restrict__ rwb,   const float* __restrict__ rrb,
    const float* __restrict__ f,
    float* __restrict__ oWin,  float* __restrict__ oWpos,
    float* __restrict__ oWout, float* __restrict__ obin,
    float* __restrict__ obpos, float* __restrict__ obout,
    float* __restrict__ orw,   float* __restrict__ orr)
{
    int idx = blockIdx.x * blockDim.x + threadIdx.x;
    if (idx >= HN7) return;
    const float* src; float* dst; int off;
    if      (idx < HN0) { src = w_in;  dst = oWin;  off = idx; }
    else if (idx < HN1) { src = w_pos; dst = oWpos; off = idx - HN0; }
    else if (idx < HN2) { src = w_out; dst = oWout; off = idx - HN1; }
    else if (idx < HN3) { src = b_in;  dst = obin;  off = idx - HN2; }
    else if (idx < HN4) { src = b_pos; dst = obpos; off = idx - HN3; }
    else if (idx < HN5) { src = b_out; dst = obout; off = idx - HN4; }
    else if (idx < HN6) { src = rwb;   dst = orw;   off = idx - HN5; }
    else                { src = rrb;   dst = orr;   off = idx - HN6; }
    const float4* wp = (const float4*)(src + (size_t)off * 8);
    float4 a = wp[0], b = wp[1];
    float4 f0 = *(const float4*)f;
    float4 f1 = *(const float4*)(f + 4);
    dst[off] = a.x*f0.x + a.y*f0.y + a.z*f0.z + a.w*f0.w
             + b.x*f1.x + b.y*f1.y + b.z*f1.z + b.w*f1.w;
}

// ---------------- 3xtf32 NT GEMM -----------------------------------------------
#define GA_H 0
#define GA_L 4608
#define GB_H 9216
#define GB_L 13824
#define GEMM_SMEM (18432 * 4)

__global__ __launch_bounds__(256) void gemm3(const float* __restrict__ A,
                                             const float* __restrict__ Bm,
                                             const float* __restrict__ bias,
                                             float* __restrict__ C,
                                             int M, int N, int K)
{
    extern __shared__ float sm[];
    int bm = blockIdx.y * 128, bn = blockIdx.x * 128;
    int tid = threadIdx.x;
    int w = tid >> 5, lane = tid & 31;
    int g = lane >> 2, tg = lane & 3;
    int wm = w & 1, wn = w >> 1;
    float acc[4][4][4] = {};

    for (int k0 = 0; k0 < K; k0 += 32) {
#pragma unroll
        for (int it = 0; it < 4; it++) {
            int t = tid + 256 * it;
            int row = t >> 3, kq = (t & 7) << 2;
            int m = bm + row;
            float4 av = (m < M) ? *(const float4*)(A + (size_t)m * K + k0 + kq)
                                : make_float4(0.f, 0.f, 0.f, 0.f);
            float4 ah, al;
            split2(av.x, ah.x, al.x); split2(av.y, ah.y, al.y);
            split2(av.z, ah.z, al.z); split2(av.w, ah.w, al.w);
            *(float4*)&sm[GA_H + row * 36 + kq] = ah;
            *(float4*)&sm[GA_L + row * 36 + kq] = al;
            float4 bv = *(const float4*)(Bm + (size_t)(bn + row) * K + k0 + kq);
            float4 bh, bl;
            split2(bv.x, bh.x, bl.x); split2(bv.y, bh.y, bl.y);
            split2(bv.z, bh.z, bl.z); split2(bv.w, bh.w, bl.w);
            *(float4*)&sm[GB_H + row * 36 + kq] = bh;
            *(float4*)&sm[GB_L + row * 36 + kq] = bl;
        }
        __syncthreads();
#pragma unroll
        for (int ks = 0; ks < 4; ks++) {
            float ah[4][4], al[4][4], bh[4][2], bl[4][2];
#pragma unroll
            for (int mi = 0; mi < 4; mi++) {
                int r0 = (wm * 64 + mi * 16 + g) * 36 + ks * 8 + tg;
                ah[mi][0] = sm[GA_H + r0];
                ah[mi][1] = sm[GA_H + r0 + 8 * 36];
                ah[mi][2] = sm[GA_H + r0 + 4];
                ah[mi][3] = sm[GA_H + r0 + 8 * 36 + 4];
                al[mi][0] = sm[GA_L + r0];
                al[mi][1] = sm[GA_L + r0 + 8 * 36];
                al[mi][2] = sm[GA_L + r0 + 4];
                al[mi][3] = sm[GA_L + r0 + 8 * 36 + 4];
            }
#pragma unroll
            for (int ni = 0; ni < 4; ni++) {
                int r0 = (wn * 32 + ni * 8 + g) * 36 + ks * 8 + tg;
                bh[ni][0] = sm[GB_H + r0];
                bh[ni][1] = sm[GB_H + r0 + 4];
                bl[ni][0] = sm[GB_L + r0];
                bl[ni][1] = sm[GB_L + r0 + 4];
            }
#pragma unroll
            for (int mi = 0; mi < 4; mi++)
#pragma unroll
                for (int ni = 0; ni < 4; ni++)
                    mma3(acc[mi][ni], ah[mi], al[mi], bh[ni], bl[ni]);
        }
        __syncthreads();
    }

#pragma unroll
    for (int mi = 0; mi < 4; mi++)
#pragma unroll
        for (int ni = 0; ni < 4; ni++) {
            int m0 = bm + wm * 64 + mi * 16 + g;
            int n0 = bn + wn * 32 + ni * 8 + tg * 2;
            float bb0 = bias[n0], bb1 = bias[n0 + 1];
            if (m0 < M) {
                float2 o = {acc[mi][ni][0] + bb0, acc[mi][ni][1] + bb1};
                *(float2*)(C + (size_t)m0 * N + n0) = o;
            }
            if (m0 + 8 < M) {
                float2 o = {acc[mi][ni][2] + bb0, acc[mi][ni][3] + bb1};
                *(float2*)(C + (size_t)(m0 + 8) * N + n0) = o;
            }
        }
}

// ---------------- fused attention: scores(rel-shift) + online softmax + PV -----
#define AQWH 0
#define AQWL 1280
#define AQRH 2560
#define AQRL 3840
#define AKH  5120
#define AKL  7680
#define ARH  10240
#define ARL  14080
#define AG   0
#define AP   0
#define AVH  8448
#define AVL  13056
#define ARMX 17920
#define ARSM 18176
#define ATTN_SMEM (18432 * 4)
#define SC_ 0.125f

__global__ __launch_bounds__(256) void attn_fused(const float* __restrict__ qkv,
                                                  const float* __restrict__ rproj,
                                                  const float* __restrict__ rw,
                                                  const float* __restrict__ rr,
                                                  float* __restrict__ att)
{
    extern __shared__ float sm[];
    const int bh = blockIdx.y;
    const int b = bh / H_, h = bh % H_;
    const int i0 = blockIdx.x * 64;
    const int tid = threadIdx.x;
    const int w = tid >> 5, lane = tid & 31;
    const int g = lane >> 2, tg = lane & 3;
    const int wi = w >> 2, wj = w & 3;

    float m_run[2][2] = {{-1e30f, -1e30f}, {-1e30f, -1e30f}};
    float l_run[2][2] = {};
    float accO[2][2][4] = {};

    for (int j0 = 0; j0 < T_; j0 += 128) {
        const int pmin = j0 - i0 + (T_ - 64);
        float accA[2][4][4] = {};
        float accG[2][6][4] = {};

        for (int c = 0; c < 4; c++) {
            const int col0 = h * D_ + c * 16;
            __syncthreads();
            {
                int il = tid >> 2, kq = (tid & 3) << 2;
                float4 qv = *(const float4*)(qkv + (size_t)((i0 + il) * B_ + b) * (3 * E_) + col0 + kq);
                float4 rwv = *(const float4*)(rw + col0 + kq);
                float4 rrv = *(const float4*)(rr + col0 + kq);
                float4 hw, lw, hr, lr;
                split2(qv.x + rwv.x, hw.x, lw.x); split2(qv.y + rwv.y, hw.y, lw.y);
                split2(qv.z + rwv.z, hw.z, lw.z); split2(qv.w + rwv.w, hw.w, lw.w);
                split2(qv.x + rrv.x, hr.x, lr.x); split2(qv.y + rrv.y, hr.y, lr.y);
                split2(qv.z + rrv.z, hr.z, lr.z); split2(qv.w + rrv.w, hr.w, lr.w);
                *(float4*)&sm[AQWH + il * 20 + kq] = hw;
                *(float4*)&sm[AQWL + il * 20 + kq] = lw;
                *(float4*)&sm[AQRH + il * 20 + kq] = hr;
                *(float4*)&sm[AQRL + il * 20 + kq] = lr;
            }
#pragma unroll
            for (int it = 0; it < 2; it++) {
                int t = tid + 256 * it;
                int il = t >> 2, kq = (t & 3) << 2;
                float4 kv = *(const float4*)(qkv + (size_t)((j0 + il) * B_ + b) * (3 * E_) + E_ + col0 + kq);
                float4 hk, lk;
                split2(kv.x, hk.x, lk.x); split2(kv.y, hk.y, lk.y);
                split2(kv.z, hk.z, lk.z); split2(kv.w, hk.w, lk.w);
                *(float4*)&sm[AKH + il * 20 + kq] = hk;
                *(float4*)&sm[AKL + il * 20 + kq] = lk;
            }
#pragma unroll
            for (int it = 0; it < 3; it++) {
                int t = tid + 256 * it;
                int pl = t >> 2, kq = (t & 3) << 2;
                float4 rv = (pl < 191)
                    ? *(const float4*)(rproj + (size_t)((pmin + pl) * B_ + b) * E_ + col0 + kq)
                    : make_float4(0.f, 0.f, 0.f, 0.f);
                float4 hh, ll;
                split2(rv.x, hh.x, ll.x); split2(rv.y, hh.y, ll.y);
                split2(rv.z, hh.z, ll.z); split2(rv.w, hh.w, ll.w);
                *(float4*)&sm[ARH + pl * 20 + kq] = hh;
                *(float4*)&sm[ARL + pl * 20 + kq] = ll;
            }
            __syncthreads();
#pragma unroll
            for (int ks = 0; ks < 2; ks++) {
                float aWh[2][4], aWl[2][4], aRh[2][4], aRl[2][4];
#pragma unroll
                for (int mi = 0; mi < 2; mi++) {
                    int r0 = (wi * 32 + mi * 16 + g) * 20 + ks * 8 + tg;
                    aWh[mi][0] = sm[AQWH + r0];
                    aWh[mi][1] = sm[AQWH + r0 + 8 * 20];
                    aWh[mi][2] = sm[AQWH + r0 + 4];
                    aWh[mi][3] = sm[AQWH + r0 + 8 * 20 + 4];
                    aWl[mi][0] = sm[AQWL + r0];
                    aWl[mi][1] = sm[AQWL + r0 + 8 * 20];
                    aWl[mi][2] = sm[AQWL + r0 + 4];
                    aWl[mi][3] = sm[AQWL + r0 + 8 * 20 + 4];
                    aRh[mi][0] = sm[AQRH + r0];
                    aRh[mi][1] = sm[AQRH + r0 + 8 * 20];
                    aRh[mi][2] = sm[AQRH + r0 + 4];
                    aRh[mi][3] = sm[AQRH + r0 + 8 * 20 + 4];
                    aRl[mi][0] = sm[AQRL + r0];
                    aRl[mi][1] = sm[AQRL + r0 + 8 * 20];
                    aRl[mi][2] = sm[AQRL + r0 + 4];
                    aRl[mi][3] = sm[AQRL + r0 + 8 * 20 + 4];
                }
#pragma unroll
                for (int nj = 0; nj < 4; nj++) {
                    float bhf[2], blf[2];
                    int r0 = (wj * 32 + nj * 8 + g) * 20 + ks * 8 + tg;
                    bhf[0] = sm[AKH + r0]; bhf[1] = sm[AKH + r0 + 4];
                    blf[0] = sm[AKL + r0]; blf[1] = sm[AKL + r0 + 4];
                    mma3(accA[0][nj], aWh[0], aWl[0], bhf, blf);
                    mma3(accA[1][nj], aWh[1], aWl[1], bhf, blf);
                }
#pragma unroll
                for (int ng = 0; ng < 6; ng++) {
                    float bhf[2], blf[2];
                    int r0 = (wj * 48 + ng * 8 + g) * 20 + ks * 8 + tg;
                    bhf[0] = sm[ARH + r0]; bhf[1] = sm[ARH + r0 + 4];
                    blf[0] = sm[ARL + r0]; blf[1] = sm[ARL + r0 + 4];
                    mma3(accG[0][ng], aRh[0], aRl[0], bhf, blf);
                    mma3(accG[1][ng], aRh[1], aRl[1], bhf, blf);
                }
            }
        }
        __syncthreads();

#pragma unroll
        for (int mi = 0; mi < 2; mi++)
#pragma unroll
            for (int ng = 0; ng < 6; ng++) {
                int row = wi * 32 + mi * 16 + g;
                int cc = wj * 48 + ng * 8 + tg * 2;
                sm[AG + row * 196 + cc]           = accG[mi][ng][0];
                sm[AG + row * 196 + cc + 1]       = accG[mi][ng][1];
                sm[AG + (row + 8) * 196 + cc]     = accG[mi][ng][2];
                sm[AG + (row + 8) * 196 + cc + 1] = accG[mi][ng][3];
            }
        __syncthreads();

        float tmax[2][2] = {{-1e30f, -1e30f}, {-1e30f, -1e30f}};
#pragma unroll
        for (int mi = 0; mi < 2; mi++)
#pragma unroll
            for (int nj = 0; nj < 4; nj++) {
                int il = wi * 32 + mi * 16 + g;
                int jl = wj * 32 + nj * 8 + tg * 2;
                int il2 = il + 8;
                accA[mi][nj][0] += sm[AG + il * 196 + (jl - il + 63)];
                accA[mi][nj][1] += sm[AG + il * 196 + (jl + 1 - il + 63)];
                accA[mi][nj][2] += sm[AG + il2 * 196 + (jl - il2 + 63)];
                accA[mi][nj][3] += sm[AG + il2 * 196 + (jl + 1 - il2 + 63)];
                tmax[mi][0] = fmaxf(tmax[mi][0], fmaxf(accA[mi][nj][0], accA[mi][nj][1]));
                tmax[mi][1] = fmaxf(tmax[mi][1], fmaxf(accA[mi][nj][2], accA[mi][nj][3]));
            }
#pragma unroll
        for (int mi = 0; mi < 2; mi++)
#pragma unroll
            for (int rp = 0; rp < 2; rp++) {
                float v = tmax[mi][rp];
                v = fmaxf(v, __shfl_xor_sync(0xffffffffu, v, 1));
                v = fmaxf(v, __shfl_xor_sync(0xffffffffu, v, 2));
                tmax[mi][rp] = v;
            }
        if (tg == 0) {
#pragma unroll
            for (int mi = 0; mi < 2; mi++)
#pragma unroll
                for (int rp = 0; rp < 2; rp++) {
                    int row = wi * 32 + mi * 16 + g + rp * 8;
                    sm[ARMX + row * 4 + wj] = tmax[mi][rp];
                }
        }
        __syncthreads();

        float mnew[2][2], fsc[2][2];
#pragma unroll
        for (int mi = 0; mi < 2; mi++)
#pragma unroll
            for (int rp = 0; rp < 2; rp++) {
                int row = wi * 32 + mi * 16 + g + rp * 8;
                float mt = fmaxf(fmaxf(sm[ARMX + row * 4 + 0], sm[ARMX + row * 4 + 1]),
                                 fmaxf(sm[ARMX + row * 4 + 2], sm[ARMX + row * 4 + 3]));
                mnew[mi][rp] = fmaxf(m_run[mi][rp], mt);
                fsc[mi][rp] = __expf((m_run[mi][rp] - mnew[mi][rp]) * SC_);
            }

        float tsum[2][2] = {};
#pragma unroll
        for (int mi = 0; mi < 2; mi++)
#pragma unroll
            for (int nj = 0; nj < 4; nj++) {
                int il = wi * 32 + mi * 16 + g;
                int jl = wj * 32 + nj * 8 + tg * 2;
                float p0 = __expf((accA[mi][nj][0] - mnew[mi][0]) * SC_);
                float p1 = __expf((accA[mi][nj][1] - mnew[mi][0]) * SC_);
                float p2 = __expf((accA[mi][nj][2] - mnew[mi][1]) * SC_);
                float p3 = __expf((accA[mi][nj][3] - mnew[mi][1]) * SC_);
                tsum[mi][0] += p0 + p1;
                tsum[mi][1] += p2 + p3;
                sm[AP + il * 132 + jl]           = __uint_as_float(f2tf(p0));
                sm[AP + il * 132 + jl + 1]       = __uint_as_float(f2tf(p1));
                sm[AP + (il + 8) * 132 + jl]     = __uint_as_float(f2tf(p2));
                sm[AP + (il + 8) * 132 + jl + 1] = __uint_as_float(f2tf(p3));
            }
#pragma unroll
        for (int mi = 0; mi < 2; mi++)
#pragma unroll
            for (int rp = 0; rp < 2; rp++) {
                float v = tsum[mi][rp];
                v += __shfl_xor_sync(0xffffffffu, v, 1);
                v += __shfl_xor_sync(0xffffffffu, v, 2);
                tsum[mi][rp] = v;
            }
        if (tg == 0) {
#pragma unroll
            for (int mi = 0; mi < 2; mi++)
#pragma unroll
                for (int rp = 0; rp < 2; rp++) {
                    int row = wi * 32 + mi * 16 + g + rp * 8;
                    sm[ARSM + row * 4 + wj] = tsum[mi][rp];
                }
        }
        __syncthreads();

#pragma unroll
        for (int mi = 0; mi < 2; mi++)
#pragma unroll
            for (int rp = 0; rp < 2; rp++) {
                int row = wi * 32 + mi * 16 + g + rp * 8;
                float lt = sm[ARSM + row * 4 + 0] + sm[ARSM + row * 4 + 1]
                         + sm[ARSM + row * 4 + 2] + sm[ARSM + row * 4 + 3];
                l_run[mi][rp] = l_run[mi][rp] * fsc[mi][rp] + lt;
                m_run[mi][rp] = mnew[mi][rp];
            }
#pragma unroll
        for (int mi = 0; mi < 2; mi++)
#pragma unroll
            for (int nd = 0; nd < 2; nd++) {
                accO[mi][nd][0] *= fsc[mi][0];
                accO[mi][nd][1] *= fsc[mi][0];
                accO[mi][nd][2] *= fsc[mi][1];
                accO[mi][nd][3] *= fsc[mi][1];
            }

        for (int jc = 0; jc < 2; jc++) {
            __syncthreads();
#pragma unroll
            for (int it = 0; it < 4; it++) {
                int t = tid + 256 * it;
                int row = t >> 4, dq = (t & 15) << 2;
                float4 vv = *(const float4*)(qkv + (size_t)((j0 + jc * 64 + row) * B_ + b) * (3 * E_)
                                             + 2 * E_ + h * D_ + dq);
                float4 hh, ll;
                split2(vv.x, hh.x, ll.x); split2(vv.y, hh.y, ll.y);
                split2(vv.z, hh.z, ll.z); split2(vv.w, hh.w, ll.w);
                *(float4*)&sm[AVH + row * 72 + dq] = hh;
                *(float4*)&sm[AVL + row * 72 + dq] = ll;
            }
            __syncthreads();
#pragma unroll
            for (int ks = 0; ks < 8; ks++) {
                float a[2][4];
#pragma unroll
                for (int mi = 0; mi < 2; mi++) {
                    int r0 = (wi * 32 + mi * 16 + g) * 132 + jc * 64 + ks * 8 + tg;
                    a[mi][0] = sm[AP + r0];
                    a[mi][1] = sm[AP + r0 + 8 * 132];
                    a[mi][2] = sm[AP + r0 + 4];
                    a[mi][3] = sm[AP + r0 + 8 * 132 + 4];
                }
#pragma unroll
                for (int nd = 0; nd < 2; nd++) {
                    int col = wj * 16 + nd * 8 + g;
                    float bhf[2], blf[2];
                    bhf[0] = sm[AVH + (ks * 8 + tg) * 72 + col];
                    bhf[1] = sm[AVH + (ks * 8 + tg + 4) * 72 + col];
                    blf[0] = sm[AVL + (ks * 8 + tg) * 72 + col];
                    blf[1] = sm[AVL + (ks * 8 + tg + 4) * 72 + col];
#pragma unroll
                    for (int mi = 0; mi < 2; mi++) {
                        mma8(accO[mi][nd], a[mi], bhf);
                        mma8(accO[mi][nd], a[mi], blf);
                    }
                }
            }
        }
    }

    float inv[2][2];
#pragma unroll
    for (int mi = 0; mi < 2; mi++)
#pragma unroll
        for (int rp = 0; rp < 2; rp++)
            inv[mi][rp] = 1.0f / l_run[mi][rp];
#pragma unroll
    for (int mi = 0; mi < 2; mi++)
#pragma unroll
        for (int nd = 0; nd < 2; nd++) {
            int row = wi * 32 + mi * 16 + g;
            int col = h * D_ + wj * 16 + nd * 8 + tg * 2;
            float2 o0 = {accO[mi][nd][0] * inv[mi][0], accO[mi][nd][1] * inv[mi][0]};
            float2 o1 = {accO[mi][nd][2] * inv[mi][1], accO[mi][nd][3] * inv[mi][1]};
            *(float2*)(att + (size_t)((i0 + row) * B_ + b) * E_ + col) = o0;
            *(float2*)(att + (size_t)((i0 + row + 8) * B_ + b) * E_ + col) = o1;
        }
}

// ---------------- launch ----------------
extern "C" void kernel_launch(void* const* d_in, const int* in_sizes, int n_in,
                              void* d_out, int out_size)
{
    (void)in_sizes; (void)n_in; (void)out_size;
    const float* input  = (const float*)d_in[0];
    const float* pos    = (const float*)d_in[1];
    const float* factor = (const float*)d_in[2];
    const float* w_in   = (const float*)d_in[3];
    const float* w_pos  = (const float*)d_in[4];
    const float* w_out  = (const float*)d_in[5];
    const float* bw_in  = (const float*)d_in[6];
    const float* bw_pos = (const float*)d_in[7];
    const float* bw_out = (const float*)d_in[8];
    const float* rwb    = (const float*)d_in[9];
    const float* rrb    = (const float*)d_in[10];

    float *pWin, *pWpos, *pWout, *pbin, *pbpos, *pbout, *prw, *prr,
          *pqkv, *pr, *patt;
    cudaGetSymbolAddress((void**)&pWin,  g_Win);
    cudaGetSymbolAddress((void**)&pWpos, g_Wpos);
    cudaGetSymbolAddress((void**)&pWout, g_Wout);
    cudaGetSymbolAddress((void**)&pbin,  g_bin);
    cudaGetSymbolAddress((void**)&pbpos, g_bpos);
    cudaGetSymbolAddress((void**)&pbout, g_bout);
    cudaGetSymbolAddress((void**)&prw,   g_rw);
    cudaGetSymbolAddress((void**)&prr,   g_rr);
    cudaGetSymbolAddress((void**)&pqkv,  g_qkv);
    cudaGetSymbolAddress((void**)&pr,    g_r);
    cudaGetSymbolAddress((void**)&patt,  g_att);

    cudaFuncSetAttribute(gemm3,      cudaFuncAttributeMaxDynamicSharedMemorySize, GEMM_SMEM);
    cudaFuncSetAttribute(attn_fused, cudaFuncAttributeMaxDynamicSharedMemorySize, ATTN_SMEM);

    // 1) hypernet (single launch)
    hyper_all<<<(HN7 + 255) / 256, 256>>>(w_in, w_pos, w_out, bw_in, bw_pos, bw_out,
                                          rwb, rrb, factor,
                                          pWin, pWpos, pWout, pbin, pbpos, pbout, prw, prr);

    // 2) projections (3xtf32)
    gemm3<<<dim3(3 * E_ / 128, TB_ / 128), 256, GEMM_SMEM>>>(input, pWin, pbin, pqkv, TB_, 3 * E_, E_);
    gemm3<<<dim3(E_ / 128, (RB_ + 127) / 128), 256, GEMM_SMEM>>>(pos, pWpos, pbpos, pr, RB_, E_, E_);

    // 3) fused attention (scores + rel-shift + online softmax + PV)
    attn_fused<<<dim3(T_ / 64, B_ * H_), 256, ATTN_SMEM>>>(pqkv, pr, prw, prr, patt);

    // 4) output projection -> d_out
    gemm3<<<dim3(E_ / 128, TB_ / 128), 256, GEMM_SMEM>>>(patt, pWout, pbout, (float*)d_out, TB_, E_, E_);
}